// round 3
// baseline (speedup 1.0000x reference)
#include <cuda_runtime.h>
#include <math.h>

#define GAMMA 0.99f
#define LAM   0.95f
#define GL    (GAMMA * LAM)
#define EPSN  1e-8

#define CHUNKS 64
#define MAXN   8192
#define MAXT   2048
#define TPB    256
#define P2BLK  (MAXN / TPB)   // 32 partial slots

// Static device scratch (no allocations allowed).
__device__ float4   g_P[CHUNKS * MAXN];              // {C, D, S1, SC}   8 MB
__device__ float4   g_Q[CHUNKS * MAXN];              // {S2, SDC, SC2,_} 8 MB
__device__ float    g_carry[CHUNKS * MAXN];          // 2 MB
__device__ unsigned g_bits[(MAXT * MAXN) / 32];      // done bitmask, 2 MB
__device__ double   g_part[2 * P2BLK];
__device__ float    g_mean;
__device__ float    g_inv;   // 1 / (std + eps)

// ---------------------------------------------------------------------------
// Phase 0: bit-pack dones. One thread per element, warp ballot -> one word
// per 32 consecutive elements. Saves ~62 MB of reads in EACH big pass.
// ---------------------------------------------------------------------------
__global__ __launch_bounds__(TPB)
void gae_pack(const int* __restrict__ dn, int TN) {
    int i = blockIdx.x * blockDim.x + threadIdx.x;
    int v = (i < TN) ? dn[i] : 0;
    unsigned w = __ballot_sync(0xFFFFFFFFu, v != 0);
    if ((threadIdx.x & 31) == 0 && i < TN) g_bits[i >> 5] = w;
}

// ---------------------------------------------------------------------------
// Phase 1: per (chunk, 2-column group), compose the reverse recurrence into
// a_out = D + C * a_in, plus sufficient statistics so global mean/std comes
// from chunk summaries alone.
// ---------------------------------------------------------------------------
__global__ __launch_bounds__(TPB)
void gae_phase1(const float* __restrict__ rw, const float* __restrict__ val,
                int N, int L) {
    int groups = N >> 1;
    int tid = blockIdx.x * blockDim.x + threadIdx.x;
    if (tid >= CHUNKS * groups) return;
    int c   = tid / groups;
    int g   = tid - c * groups;
    int col = g << 1;
    int t0  = c * L;
    int t1  = t0 + L - 1;
    int shift = col & 31;
    int nw    = N >> 5;
    int wi    = col >> 5;

    float C0 = 1.f, C1 = 1.f, D0 = 0.f, D1 = 0.f;
    float S10 = 0.f, S11 = 0.f, SC0 = 0.f, SC1 = 0.f;
    float S20 = 0.f, S21 = 0.f, SDC0 = 0.f, SDC1 = 0.f, SC20 = 0.f, SC21 = 0.f;

    float2 vn = *reinterpret_cast<const float2*>(val + (size_t)(t1 + 1) * N + col);
    #pragma unroll 8
    for (int t = t1; t >= t0; --t) {
        float2   r  = *reinterpret_cast<const float2*>(rw + (size_t)t * N + col);
        float2   vc = *reinterpret_cast<const float2*>(val + (size_t)t * N + col);
        unsigned w  = g_bits[t * nw + wi];

        float nt0 = ((w >> shift) & 1u) ? 0.f : 1.f;
        float nt1 = ((w >> (shift + 1)) & 1u) ? 0.f : 1.f;
        float del0 = fmaf(GAMMA * nt0, vn.x, r.x) - vc.x;
        float del1 = fmaf(GAMMA * nt1, vn.y, r.y) - vc.y;
        float cf0 = GL * nt0, cf1 = GL * nt1;

        D0 = fmaf(cf0, D0, del0);  C0 *= cf0;
        D1 = fmaf(cf1, D1, del1);  C1 *= cf1;
        S10 += D0;  S11 += D1;
        SC0 += C0;  SC1 += C1;
        S20  = fmaf(D0, D0, S20);   S21  = fmaf(D1, D1, S21);
        SDC0 = fmaf(D0, C0, SDC0);  SDC1 = fmaf(D1, C1, SDC1);
        SC20 = fmaf(C0, C0, SC20);  SC21 = fmaf(C1, C1, SC21);

        vn = vc;
    }
    size_t o = (size_t)c * N + col;
    g_P[o]     = make_float4(C0, D0, S10, SC0);
    g_P[o + 1] = make_float4(C1, D1, S11, SC1);
    g_Q[o]     = make_float4(S20, SDC0, SC20, 0.f);
    g_Q[o + 1] = make_float4(S21, SDC1, SC21, 0.f);
}

// ---------------------------------------------------------------------------
// Phase 2: one thread per column. Reverse-scan CHUNKS chunk summaries to
// produce carries + the column's total sum/sumsq via closed forms:
//   sum_chunk   = S1 + SC*a
//   sumsq_chunk = S2 + 2*SDC*a + SC2*a*a
// ---------------------------------------------------------------------------
__global__ __launch_bounds__(TPB)
void gae_phase2(int N) {
    int col = blockIdx.x * blockDim.x + threadIdx.x;
    float ts = 0.f, ts2 = 0.f;
    if (col < N) {
        float a = 0.f;
        #pragma unroll 8
        for (int c = CHUNKS - 1; c >= 0; --c) {
            size_t o = (size_t)c * N + col;
            g_carry[o] = a;
            float4 P = g_P[o];
            float4 Q = g_Q[o];
            ts  += fmaf(P.w, a, P.z);
            ts2 += fmaf(fmaf(Q.z, a, 2.f * Q.y), a, Q.x);
            a = fmaf(P.x, a, P.y);
        }
    }
    __shared__ double ss[TPB];
    __shared__ double ss2[TPB];
    ss[threadIdx.x]  = (double)ts;
    ss2[threadIdx.x] = (double)ts2;
    __syncthreads();
    for (int st = TPB / 2; st > 0; st >>= 1) {
        if (threadIdx.x < st) {
            ss[threadIdx.x]  += ss[threadIdx.x + st];
            ss2[threadIdx.x] += ss2[threadIdx.x + st];
        }
        __syncthreads();
    }
    if (threadIdx.x == 0) {
        g_part[2 * blockIdx.x]     = ss[0];
        g_part[2 * blockIdx.x + 1] = ss2[0];
    }
}

// ---------------------------------------------------------------------------
// Finalize stats: single tiny block -> mean, 1/(std+eps), ddof=1.
// ---------------------------------------------------------------------------
__global__ void gae_finalize(int nblocks, long long M) {
    __shared__ double ss[64];
    __shared__ double ss2[64];
    double s = 0.0, s2 = 0.0;
    for (int i = threadIdx.x; i < nblocks; i += 64) {
        s  += g_part[2 * i];
        s2 += g_part[2 * i + 1];
    }
    ss[threadIdx.x]  = s;
    ss2[threadIdx.x] = s2;
    __syncthreads();
    for (int st = 32; st > 0; st >>= 1) {
        if (threadIdx.x < st) {
            ss[threadIdx.x]  += ss[threadIdx.x + st];
            ss2[threadIdx.x] += ss2[threadIdx.x + st];
        }
        __syncthreads();
    }
    if (threadIdx.x == 0) {
        double mean = ss[0] / (double)M;
        double var  = (ss2[0] - ss[0] * ss[0] / (double)M) / (double)(M - 1);
        if (var < 0.0) var = 0.0;
        g_mean = (float)mean;
        g_inv  = (float)(1.0 / (sqrt(var) + EPSN));
    }
}

// ---------------------------------------------------------------------------
// Write pass: replay recurrence with correct carry; emit NORMALIZED
// advantages and returns directly. No FP64, no reductions.
// ---------------------------------------------------------------------------
__global__ __launch_bounds__(TPB)
void gae_write(const float* __restrict__ rw, const float* __restrict__ val,
               float* __restrict__ adv, float* __restrict__ ret,
               int N, int L) {
    int groups = N >> 1;
    int tid = blockIdx.x * blockDim.x + threadIdx.x;
    if (tid >= CHUNKS * groups) return;
    int c   = tid / groups;
    int g   = tid - c * groups;
    int col = g << 1;
    int t0  = c * L;
    int t1  = t0 + L - 1;
    int shift = col & 31;
    int nw    = N >> 5;
    int wi    = col >> 5;

    float m   = g_mean;
    float inv = g_inv;

    float2 a  = *reinterpret_cast<const float2*>(g_carry + (size_t)c * N + col);
    float2 vn = *reinterpret_cast<const float2*>(val + (size_t)(t1 + 1) * N + col);

    #pragma unroll 8
    for (int t = t1; t >= t0; --t) {
        float2   r  = *reinterpret_cast<const float2*>(rw + (size_t)t * N + col);
        float2   vc = *reinterpret_cast<const float2*>(val + (size_t)t * N + col);
        unsigned w  = g_bits[t * nw + wi];

        float nt0 = ((w >> shift) & 1u) ? 0.f : 1.f;
        float nt1 = ((w >> (shift + 1)) & 1u) ? 0.f : 1.f;
        float del0 = fmaf(GAMMA * nt0, vn.x, r.x) - vc.x;
        float del1 = fmaf(GAMMA * nt1, vn.y, r.y) - vc.y;
        a.x = fmaf(GL * nt0, a.x, del0);
        a.y = fmaf(GL * nt1, a.y, del1);

        size_t o = (size_t)t * N + col;
        *reinterpret_cast<float2*>(adv + o) =
            make_float2((a.x - m) * inv, (a.y - m) * inv);
        *reinterpret_cast<float2*>(ret + o) =
            make_float2(a.x + vc.x, a.y + vc.y);

        vn = vc;
    }
}

extern "C" void kernel_launch(void* const* d_in, const int* in_sizes, int n_in,
                              void* d_out, int out_size) {
    const float* rw  = (const float*)d_in[0];   // rewards [T, N]
    const float* val = (const float*)d_in[1];   // values  [T+1, N]
    const int*   dn  = (const int*)d_in[2];     // dones   [T, N]
    float* out = (float*)d_out;                 // [adv_norm TN | returns TN]

    int TN = in_sizes[0];
    int N  = in_sizes[1] - in_sizes[0];
    int T  = TN / N;
    int L  = T / CHUNKS;

    int groups  = N >> 1;
    int nth     = CHUNKS * groups;
    int blocks1 = (nth + TPB - 1) / TPB;
    int blocks2 = (N + TPB - 1) / TPB;

    float* adv = out;
    float* ret = out + (size_t)TN;

    gae_pack<<<(TN + TPB - 1) / TPB, TPB>>>(dn, TN);
    gae_phase1<<<blocks1, TPB>>>(rw, val, N, L);
    gae_phase2<<<blocks2, TPB>>>(N);
    gae_finalize<<<1, 64>>>(blocks2, (long long)TN);
    gae_write<<<blocks1, TPB>>>(rw, val, adv, ret, N, L);
}

// round 4
// speedup vs baseline: 1.1105x; 1.1105x over previous
#include <cuda_runtime.h>
#include <math.h>

#define GAMMA 0.99f
#define LAM   0.95f
#define GL    (GAMMA * LAM)
#define EPSN  1e-8

#define CHUNKS 128
#define MAXN   8192
#define MAXT   2048
#define TPB    256
#define P2BLK  (MAXN / TPB)   // 32 partial slots

// Static device scratch (no allocations allowed).
__device__ float4   g_P[CHUNKS * MAXN];          // {C, D, S1, SC}    16 MB
__device__ float4   g_Q[CHUNKS * MAXN];          // {S2, SDC, SC2,_}  16 MB
__device__ float    g_carry[CHUNKS * MAXN];      // 4 MB
__device__ unsigned g_bits[(MAXT * MAXN) / 32];  // done bits (interleaved layout), 2 MB
__device__ double   g_part[2 * P2BLK];
__device__ float    g_mean;
__device__ float    g_inv;   // 1 / (std + eps)

// Bit layout contract (writer = phase1, reader = gae_write, identical thread
// mapping): for warp covering columns [colbase, colbase+128), word j of the
// uint4 at g_bits[t*(N/32) + colbase/32] has bit l = done(t, colbase + 4l + j).

// ---------------------------------------------------------------------------
// Phase 1: per (chunk, 4-column group), compose the reverse recurrence into
// a_out = D + C * a_in, accumulate sufficient statistics for global mean/std,
// and bit-pack dones for the write pass (4 ballots + one STG.128 per warp/t).
// ---------------------------------------------------------------------------
__global__ __launch_bounds__(TPB)
void gae_phase1(const float* __restrict__ rw, const float* __restrict__ val,
                const int* __restrict__ dn, int N, int L) {
    int groups = N >> 2;
    int tid = blockIdx.x * blockDim.x + threadIdx.x;
    if (tid >= CHUNKS * groups) return;
    int c    = tid / groups;
    int g    = tid - c * groups;
    int col  = g << 2;
    int lane = threadIdx.x & 31;
    int colbase  = col - (lane << 2);
    int wordbase = colbase >> 5;
    int nw   = N >> 5;
    int t0   = c * L;
    int t1   = t0 + L - 1;

    float C[4]  = {1.f, 1.f, 1.f, 1.f};
    float D[4]  = {0.f, 0.f, 0.f, 0.f};
    float S1[4] = {0.f, 0.f, 0.f, 0.f};
    float SC[4] = {0.f, 0.f, 0.f, 0.f};
    float S2[4] = {0.f, 0.f, 0.f, 0.f};
    float SDC[4]= {0.f, 0.f, 0.f, 0.f};
    float SC2[4]= {0.f, 0.f, 0.f, 0.f};

    float4 vn = __ldcs(reinterpret_cast<const float4*>(val + (size_t)(t1 + 1) * N + col));
    #pragma unroll 4
    for (int t = t1; t >= t0; --t) {
        float4 r  = __ldcs(reinterpret_cast<const float4*>(rw + (size_t)t * N + col));
        int4   dd = __ldcs(reinterpret_cast<const int4*>(dn + (size_t)t * N + col));
        float4 vc = __ldcs(reinterpret_cast<const float4*>(val + (size_t)t * N + col));

        unsigned b0 = __ballot_sync(0xFFFFFFFFu, dd.x != 0);
        unsigned b1 = __ballot_sync(0xFFFFFFFFu, dd.y != 0);
        unsigned b2 = __ballot_sync(0xFFFFFFFFu, dd.z != 0);
        unsigned b3 = __ballot_sync(0xFFFFFFFFu, dd.w != 0);
        if (lane == 0)
            *reinterpret_cast<uint4*>(g_bits + (size_t)t * nw + wordbase) =
                make_uint4(b0, b1, b2, b3);

        float rr[4] = {r.x, r.y, r.z, r.w};
        float vv[4] = {vc.x, vc.y, vc.z, vc.w};
        float vnn[4]= {vn.x, vn.y, vn.z, vn.w};
        int   di[4] = {dd.x, dd.y, dd.z, dd.w};

        #pragma unroll
        for (int j = 0; j < 4; ++j) {
            float nt  = di[j] ? 0.f : 1.f;
            float del = fmaf(GAMMA * nt, vnn[j], rr[j]) - vv[j];
            float cf  = GL * nt;
            D[j] = fmaf(cf, D[j], del);
            C[j] *= cf;
            S1[j] += D[j];
            SC[j] += C[j];
            S2[j]  = fmaf(D[j], D[j], S2[j]);
            SDC[j] = fmaf(D[j], C[j], SDC[j]);
            SC2[j] = fmaf(C[j], C[j], SC2[j]);
        }
        vn = vc;
    }
    size_t o = (size_t)c * N + col;
    #pragma unroll
    for (int j = 0; j < 4; ++j) {
        g_P[o + j] = make_float4(C[j], D[j], S1[j], SC[j]);
        g_Q[o + j] = make_float4(S2[j], SDC[j], SC2[j], 0.f);
    }
}

// ---------------------------------------------------------------------------
// Phase 2: one thread per column. Reverse-scan CHUNKS chunk summaries to
// produce carries + the column's total sum/sumsq via closed forms:
//   sum_chunk   = S1 + SC*a ;  sumsq_chunk = S2 + 2*SDC*a + SC2*a*a
// ---------------------------------------------------------------------------
__global__ __launch_bounds__(TPB)
void gae_phase2(int N) {
    int col = blockIdx.x * blockDim.x + threadIdx.x;
    float ts = 0.f, ts2 = 0.f;
    if (col < N) {
        float a = 0.f;
        #pragma unroll 8
        for (int c = CHUNKS - 1; c >= 0; --c) {
            size_t o = (size_t)c * N + col;
            g_carry[o] = a;
            float4 P = g_P[o];
            float4 Q = g_Q[o];
            ts  += fmaf(P.w, a, P.z);
            ts2 += fmaf(fmaf(Q.z, a, 2.f * Q.y), a, Q.x);
            a = fmaf(P.x, a, P.y);
        }
    }
    __shared__ double ss[TPB];
    __shared__ double ss2[TPB];
    ss[threadIdx.x]  = (double)ts;
    ss2[threadIdx.x] = (double)ts2;
    __syncthreads();
    for (int st = TPB / 2; st > 0; st >>= 1) {
        if (threadIdx.x < st) {
            ss[threadIdx.x]  += ss[threadIdx.x + st];
            ss2[threadIdx.x] += ss2[threadIdx.x + st];
        }
        __syncthreads();
    }
    if (threadIdx.x == 0) {
        g_part[2 * blockIdx.x]     = ss[0];
        g_part[2 * blockIdx.x + 1] = ss2[0];
    }
}

// ---------------------------------------------------------------------------
// Finalize stats: single tiny block -> mean, 1/(std+eps), ddof=1.
// ---------------------------------------------------------------------------
__global__ void gae_finalize(int nblocks, long long M) {
    __shared__ double ss[64];
    __shared__ double ss2[64];
    double s = 0.0, s2 = 0.0;
    for (int i = threadIdx.x; i < nblocks; i += 64) {
        s  += g_part[2 * i];
        s2 += g_part[2 * i + 1];
    }
    ss[threadIdx.x]  = s;
    ss2[threadIdx.x] = s2;
    __syncthreads();
    for (int st = 32; st > 0; st >>= 1) {
        if (threadIdx.x < st) {
            ss[threadIdx.x]  += ss[threadIdx.x + st];
            ss2[threadIdx.x] += ss2[threadIdx.x + st];
        }
        __syncthreads();
    }
    if (threadIdx.x == 0) {
        double mean = ss[0] / (double)M;
        double var  = (ss2[0] - ss[0] * ss[0] / (double)M) / (double)(M - 1);
        if (var < 0.0) var = 0.0;
        g_mean = (float)mean;
        g_inv  = (float)(1.0 / (sqrt(var) + EPSN));
    }
}

// ---------------------------------------------------------------------------
// Write pass: replay recurrence with correct carry; read dones from the 2 MB
// bitmask (one broadcast LDG.128 per warp per t); emit NORMALIZED advantages
// and returns with streaming stores.
// ---------------------------------------------------------------------------
__global__ __launch_bounds__(TPB)
void gae_write(const float* __restrict__ rw, const float* __restrict__ val,
               float* __restrict__ adv, float* __restrict__ ret,
               int N, int L) {
    int groups = N >> 2;
    int tid = blockIdx.x * blockDim.x + threadIdx.x;
    if (tid >= CHUNKS * groups) return;
    int c    = tid / groups;
    int g    = tid - c * groups;
    int col  = g << 2;
    int lane = threadIdx.x & 31;
    int colbase  = col - (lane << 2);
    int wordbase = colbase >> 5;
    int nw   = N >> 5;
    int t0   = c * L;
    int t1   = t0 + L - 1;

    float m   = g_mean;
    float inv = g_inv;

    float4 a  = *reinterpret_cast<const float4*>(g_carry + (size_t)c * N + col);
    float4 vn = __ldcs(reinterpret_cast<const float4*>(val + (size_t)(t1 + 1) * N + col));

    #pragma unroll 4
    for (int t = t1; t >= t0; --t) {
        float4 r  = __ldcs(reinterpret_cast<const float4*>(rw + (size_t)t * N + col));
        float4 vc = __ldcs(reinterpret_cast<const float4*>(val + (size_t)t * N + col));
        uint4  bw = *reinterpret_cast<const uint4*>(g_bits + (size_t)t * nw + wordbase);

        float nt0 = ((bw.x >> lane) & 1u) ? 0.f : 1.f;
        float nt1 = ((bw.y >> lane) & 1u) ? 0.f : 1.f;
        float nt2 = ((bw.z >> lane) & 1u) ? 0.f : 1.f;
        float nt3 = ((bw.w >> lane) & 1u) ? 0.f : 1.f;

        a.x = fmaf(GL * nt0, a.x, fmaf(GAMMA * nt0, vn.x, r.x) - vc.x);
        a.y = fmaf(GL * nt1, a.y, fmaf(GAMMA * nt1, vn.y, r.y) - vc.y);
        a.z = fmaf(GL * nt2, a.z, fmaf(GAMMA * nt2, vn.z, r.z) - vc.z);
        a.w = fmaf(GL * nt3, a.w, fmaf(GAMMA * nt3, vn.w, r.w) - vc.w);

        size_t o = (size_t)t * N + col;
        __stcs(reinterpret_cast<float4*>(adv + o),
               make_float4((a.x - m) * inv, (a.y - m) * inv,
                           (a.z - m) * inv, (a.w - m) * inv));
        __stcs(reinterpret_cast<float4*>(ret + o),
               make_float4(a.x + vc.x, a.y + vc.y, a.z + vc.z, a.w + vc.w));

        vn = vc;
    }
}

extern "C" void kernel_launch(void* const* d_in, const int* in_sizes, int n_in,
                              void* d_out, int out_size) {
    const float* rw  = (const float*)d_in[0];   // rewards [T, N]
    const float* val = (const float*)d_in[1];   // values  [T+1, N]
    const int*   dn  = (const int*)d_in[2];     // dones   [T, N]
    float* out = (float*)d_out;                 // [adv_norm TN | returns TN]

    int TN = in_sizes[0];
    int N  = in_sizes[1] - in_sizes[0];
    int T  = TN / N;
    int L  = T / CHUNKS;

    int groups  = N >> 2;
    int nth     = CHUNKS * groups;
    int blocks1 = (nth + TPB - 1) / TPB;
    int blocks2 = (N + TPB - 1) / TPB;

    float* adv = out;
    float* ret = out + (size_t)TN;

    gae_phase1<<<blocks1, TPB>>>(rw, val, dn, N, L);
    gae_phase2<<<blocks2, TPB>>>(N);
    gae_finalize<<<1, 64>>>(blocks2, (long long)TN);
    gae_write<<<blocks1, TPB>>>(rw, val, adv, ret, N, L);
}